// round 12
// baseline (speedup 1.0000x reference)
#include <cuda_runtime.h>

#define CIN  16
#define COUT 32
#define BSZ  8
#define S    24
#define SS   576
#define EPS  1e-5f

__device__ float g_mid[BSZ * SS * COUT * SS];
__device__ float g_stats[BSZ * 4 * 2];
__device__ float g_scale[BSZ * COUT];
__device__ float g_shift[BSZ * COUT];

__global__ void zero_stats_kernel() {
    if (threadIdx.x < BSZ * 8) g_stats[threadIdx.x] = 0.f;
}

// ---------------------------------------------------------------------------
// conv2: identical to the passing R6/R9 version.
// ---------------------------------------------------------------------------
__global__ __launch_bounds__(512, 1)
void conv2_kernel(const float* __restrict__ x, const float* __restrict__ w2,
                  const float* __restrict__ b2) {
    extern __shared__ float sm[];
    float* s_img = sm;                  // [16][26][26] = 10816
    float* s_w   = sm + 10816;          // [ci][tap][co] = 4608
    float* s_red = sm + 10816 + 4608;   // 8

    const int bid  = blockIdx.x;
    const int b    = bid / SS;
    const int hawa = bid % SS;
    const int tid  = threadIdx.x;

    if (tid < 8) s_red[tid] = 0.f;
    for (int i = tid; i < CIN * 26 * 26; i += 512) s_img[i] = 0.f;
    for (int i = tid; i < CIN * 9 * COUT; i += 512) {
        int ci = i / 288; int tap = (i >> 5) % 9; int co = i & 31;
        s_w[i] = w2[(co * CIN + ci) * 9 + tap];
    }
    __syncthreads();
    for (int i = tid; i < CIN * SS; i += 512) {
        int ci = i / SS; int p = i - ci * SS;
        int hb = p / S, wb = p - hb * S;
        s_img[ci * 676 + (hb + 1) * 26 + (wb + 1)] =
            x[(((long)b * CIN + ci) * SS + hawa) * SS + p];
    }
    __syncthreads();

    const int cg = tid >> 6;
    const int pt = tid & 63;
    const int py = (pt >> 3) * 3;
    const int px = (pt & 7) * 3;

    float acc[9][4];
    #pragma unroll
    for (int j = 0; j < 4; j++) {
        float bb = __ldg(&b2[cg * 4 + j]);
        #pragma unroll
        for (int p = 0; p < 9; p++) acc[p][j] = bb;
    }

    for (int ci = 0; ci < CIN; ci++) {
        float wr[4][9];
        #pragma unroll
        for (int t = 0; t < 9; t++) {
            float4 wv = *(const float4*)&s_w[(ci * 9 + t) * 32 + cg * 4];
            wr[0][t] = wv.x; wr[1][t] = wv.y; wr[2][t] = wv.z; wr[3][t] = wv.w;
        }
        float in[5][5];
        #pragma unroll
        for (int dy = 0; dy < 5; dy++)
            #pragma unroll
            for (int dx = 0; dx < 5; dx++)
                in[dy][dx] = s_img[ci * 676 + (py + dy) * 26 + (px + dx)];
        #pragma unroll
        for (int oy = 0; oy < 3; oy++)
          #pragma unroll
          for (int ox = 0; ox < 3; ox++)
            #pragma unroll
            for (int ky = 0; ky < 3; ky++)
              #pragma unroll
              for (int kx = 0; kx < 3; kx++) {
                float v = in[oy + ky][ox + kx];
                int t = ky * 3 + kx;
                #pragma unroll
                for (int j = 0; j < 4; j++)
                    acc[oy * 3 + ox][j] += v * wr[j][t];
              }
    }

    float s = 0.f, sq = 0.f;
    float* midb = g_mid + (long)(b * SS + hawa) * COUT * SS;
    #pragma unroll
    for (int oy = 0; oy < 3; oy++)
      #pragma unroll
      for (int ox = 0; ox < 3; ox++) {
        int hbwb = (py + oy) * S + (px + ox);
        #pragma unroll
        for (int j = 0; j < 4; j++) {
            float v = acc[oy * 3 + ox][j];
            s += v; sq += v * v;
            midb[(cg * 4 + j) * SS + hbwb] = v;
        }
      }
    atomicAdd(&s_red[(cg >> 1) * 2],     s);
    atomicAdd(&s_red[(cg >> 1) * 2 + 1], sq);
    __syncthreads();
    if (tid < 8) atomicAdd(&g_stats[b * 8 + tid], s_red[tid]);
}

// ---------------------------------------------------------------------------
__global__ void finalize_kernel(const float* __restrict__ gamma,
                                const float* __restrict__ beta) {
    int tid = threadIdx.x;
    if (tid >= BSZ * COUT) return;
    int b = tid >> 5, c = tid & 31, g = c >> 3;
    const float n = (float)(8 * SS * SS);
    float s  = g_stats[b * 8 + g * 2];
    float ss = g_stats[b * 8 + g * 2 + 1];
    float mean = s / n;
    float var  = ss / n - mean * mean;
    float sc = gamma[c] * rsqrtf(var + EPS);
    g_scale[tid] = sc;
    g_shift[tid] = beta[c] - mean * sc;
}

// ---------------------------------------------------------------------------
// conv1: 2x4 (ha,wa) tile x 32-lane chunk. 256 threads = 4 co-groups (8 co)
// x 4 strip-positions (2 py x 2 px-strips of 1x2 outputs) x 16 lane-pairs.
// Per thread per ci: 30 LDS feed 288 FFMAs. Weights staged in 8-ci chunks.
// smem 107.8 KB -> 2 CTAs/SM.
// ---------------------------------------------------------------------------
__global__ __launch_bounds__(256, 2)
void conv1_kernel(const float* __restrict__ w1, const float* __restrict__ b1,
                  float* __restrict__ out) {
    extern __shared__ float sm[];
    float* s_in = sm;                   // [24 coords][32 ci][32 lanes] = 24576
    float* s_w  = sm + 24576;           // [8 ci][9 tap][32 co] = 2304
    float* s_sc = sm + 24576 + 2304;    // 32
    float* s_sh = s_sc + 32;            // 32

    const int bid   = blockIdx.x;
    const int b     = bid / 1296;
    const int r     = bid - b * 1296;
    const int tile  = r / 18, chunk = r - (r / 18) * 18;
    const int ha0   = (tile / 6) * 2;       // 12 ha tiles of 2
    const int wa0   = (tile % 6) * 4;       // 6 wa tiles of 4
    const int lane0 = chunk * 32;
    const int tid   = threadIdx.x;

    if (tid < 32) {
        s_sc[tid] = g_scale[b * 32 + tid];
        s_sh[tid] = g_shift[b * 32 + tid];
    }
    __syncthreads();

    // stage inputs with GN + ReLU; zero-pad halo. 24 coords = 4 rows x 6 cols
    for (int idx = tid; idx < 24 * 32 * 32; idx += 256) {
        int lane  = idx & 31;
        int ci    = (idx >> 5) & 31;
        int coord = idx >> 10;
        int cy = ha0 - 1 + coord / 6;
        int cx = wa0 - 1 + coord % 6;
        float v = 0.f;
        if ((unsigned)cy < S && (unsigned)cx < S) {
            float m = g_mid[((long)(b * SS + cy * S + cx) * COUT + ci) * SS + lane0 + lane];
            v = fmaxf(fmaf(m, s_sc[ci], s_sh[ci]), 0.f);
        }
        s_in[idx] = v;
    }

    const int cg  = tid >> 6;          // warp-uniform co-group (8 co)
    const int sp  = (tid >> 4) & 3;    // 0..3: py | px-strip
    const int lg  = tid & 15;          // 16 lane-pairs
    const int py  = sp >> 1;
    const int px0 = (sp & 1) * 2;      // strip covers px0, px0+1
    const int l0  = lg * 2;
    const int co0 = cg * 8;

    float acc[8][2][2];                // [co][pos][lane]
    #pragma unroll
    for (int j = 0; j < 8; j++) {
        float bb = __ldg(&b1[co0 + j]);
        acc[j][0][0] = bb; acc[j][0][1] = bb;
        acc[j][1][0] = bb; acc[j][1][1] = bb;
    }

    for (int c4 = 0; c4 < 4; c4++) {
        __syncthreads();
        for (int i = tid; i < 8 * 9 * COUT; i += 256) {
            int ci = (i / 288) + c4 * 8; int t = (i >> 5) % 9; int co = i & 31;
            s_w[i] = w1[(co * COUT + ci) * 9 + t];
        }
        __syncthreads();

        for (int ci8 = 0; ci8 < 8; ci8++) {
            int ci = c4 * 8 + ci8;
            float2 in2[3][4];
            #pragma unroll
            for (int ky = 0; ky < 3; ky++)
                #pragma unroll
                for (int c = 0; c < 4; c++) {
                    int coord = (py + ky) * 6 + px0 + c;
                    in2[ky][c] = *(const float2*)&s_in[(coord * 32 + ci) * 32 + l0];
                }
            #pragma unroll
            for (int ky = 0; ky < 3; ky++)
              #pragma unroll
              for (int kx = 0; kx < 3; kx++) {
                int t = ky * 3 + kx;
                float4 wA = *(const float4*)&s_w[ci8 * 288 + t * 32 + co0];
                float4 wB = *(const float4*)&s_w[ci8 * 288 + t * 32 + co0 + 4];
                float ax = in2[ky][kx].x,     ay = in2[ky][kx].y;      // pos 0
                float bx = in2[ky][kx + 1].x, by = in2[ky][kx + 1].y;  // pos 1
                acc[0][0][0] += ax * wA.x; acc[0][0][1] += ay * wA.x;
                acc[0][1][0] += bx * wA.x; acc[0][1][1] += by * wA.x;
                acc[1][0][0] += ax * wA.y; acc[1][0][1] += ay * wA.y;
                acc[1][1][0] += bx * wA.y; acc[1][1][1] += by * wA.y;
                acc[2][0][0] += ax * wA.z; acc[2][0][1] += ay * wA.z;
                acc[2][1][0] += bx * wA.z; acc[2][1][1] += by * wA.z;
                acc[3][0][0] += ax * wA.w; acc[3][0][1] += ay * wA.w;
                acc[3][1][0] += bx * wA.w; acc[3][1][1] += by * wA.w;
                acc[4][0][0] += ax * wB.x; acc[4][0][1] += ay * wB.x;
                acc[4][1][0] += bx * wB.x; acc[4][1][1] += by * wB.x;
                acc[5][0][0] += ax * wB.y; acc[5][0][1] += ay * wB.y;
                acc[5][1][0] += bx * wB.y; acc[5][1][1] += by * wB.y;
                acc[6][0][0] += ax * wB.z; acc[6][0][1] += ay * wB.z;
                acc[6][1][0] += bx * wB.z; acc[6][1][1] += by * wB.z;
                acc[7][0][0] += ax * wB.w; acc[7][0][1] += ay * wB.w;
                acc[7][1][0] += bx * wB.w; acc[7][1][1] += by * wB.w;
              }
        }
    }

    #pragma unroll
    for (int pw = 0; pw < 2; pw++) {
        int hawa = (ha0 + py) * S + wa0 + px0 + pw;
        #pragma unroll
        for (int j = 0; j < 8; j++) {
            float2 o = make_float2(acc[j][pw][0], acc[j][pw][1]);
            *(float2*)&out[((long)(b * COUT + co0 + j) * SS + hawa) * SS + lane0 + l0] = o;
        }
    }
}

// ---------------------------------------------------------------------------
extern "C" void kernel_launch(void* const* d_in, const int* in_sizes, int n_in,
                              void* d_out, int out_size) {
    const float* x   = (const float*)d_in[0];
    const float* w1  = (const float*)d_in[1];
    const float* b1  = (const float*)d_in[2];
    const float* w2  = (const float*)d_in[3];
    const float* b2  = (const float*)d_in[4];
    const float* gam = (const float*)d_in[5];
    const float* bet = (const float*)d_in[6];
    float* out = (float*)d_out;

    const int smem2 = (10816 + 4608 + 8) * 4;            // 61,728 B
    const int smem1 = (24576 + 2304 + 64) * 4;           // 107,776 B
    cudaFuncSetAttribute(conv2_kernel, cudaFuncAttributeMaxDynamicSharedMemorySize, smem2);
    cudaFuncSetAttribute(conv1_kernel, cudaFuncAttributeMaxDynamicSharedMemorySize, smem1);

    zero_stats_kernel<<<1, 64>>>();
    conv2_kernel<<<BSZ * SS, 512, smem2>>>(x, w2, b2);
    finalize_kernel<<<1, 256>>>(gam, bet);
    conv1_kernel<<<BSZ * 144 * 9, 256, smem1>>>(w1, b1, out);
}

// round 14
// speedup vs baseline: 1.0124x; 1.0124x over previous
#include <cuda_runtime.h>

#define CIN  16
#define COUT 32
#define BSZ  8
#define S    24
#define SS   576
#define EPS  1e-5f

__device__ float g_mid[BSZ * SS * COUT * SS];
__device__ float g_stats[BSZ * 4 * 2];
__device__ float g_scale[BSZ * COUT];
__device__ float g_shift[BSZ * COUT];

__global__ void zero_stats_kernel() {
    if (threadIdx.x < BSZ * 8) g_stats[threadIdx.x] = 0.f;
}

// ---------------------------------------------------------------------------
// conv2: identical to the passing R6/R9 version.
// ---------------------------------------------------------------------------
__global__ __launch_bounds__(512, 1)
void conv2_kernel(const float* __restrict__ x, const float* __restrict__ w2,
                  const float* __restrict__ b2) {
    extern __shared__ float sm[];
    float* s_img = sm;                  // [16][26][26] = 10816
    float* s_w   = sm + 10816;          // [ci][tap][co] = 4608
    float* s_red = sm + 10816 + 4608;   // 8

    const int bid  = blockIdx.x;
    const int b    = bid / SS;
    const int hawa = bid % SS;
    const int tid  = threadIdx.x;

    if (tid < 8) s_red[tid] = 0.f;
    for (int i = tid; i < CIN * 26 * 26; i += 512) s_img[i] = 0.f;
    for (int i = tid; i < CIN * 9 * COUT; i += 512) {
        int ci = i / 288; int tap = (i >> 5) % 9; int co = i & 31;
        s_w[i] = w2[(co * CIN + ci) * 9 + tap];
    }
    __syncthreads();
    for (int i = tid; i < CIN * SS; i += 512) {
        int ci = i / SS; int p = i - ci * SS;
        int hb = p / S, wb = p - hb * S;
        s_img[ci * 676 + (hb + 1) * 26 + (wb + 1)] =
            x[(((long)b * CIN + ci) * SS + hawa) * SS + p];
    }
    __syncthreads();

    const int cg = tid >> 6;
    const int pt = tid & 63;
    const int py = (pt >> 3) * 3;
    const int px = (pt & 7) * 3;

    float acc[9][4];
    #pragma unroll
    for (int j = 0; j < 4; j++) {
        float bb = __ldg(&b2[cg * 4 + j]);
        #pragma unroll
        for (int p = 0; p < 9; p++) acc[p][j] = bb;
    }

    for (int ci = 0; ci < CIN; ci++) {
        float wr[4][9];
        #pragma unroll
        for (int t = 0; t < 9; t++) {
            float4 wv = *(const float4*)&s_w[(ci * 9 + t) * 32 + cg * 4];
            wr[0][t] = wv.x; wr[1][t] = wv.y; wr[2][t] = wv.z; wr[3][t] = wv.w;
        }
        float in[5][5];
        #pragma unroll
        for (int dy = 0; dy < 5; dy++)
            #pragma unroll
            for (int dx = 0; dx < 5; dx++)
                in[dy][dx] = s_img[ci * 676 + (py + dy) * 26 + (px + dx)];
        #pragma unroll
        for (int oy = 0; oy < 3; oy++)
          #pragma unroll
          for (int ox = 0; ox < 3; ox++)
            #pragma unroll
            for (int ky = 0; ky < 3; ky++)
              #pragma unroll
              for (int kx = 0; kx < 3; kx++) {
                float v = in[oy + ky][ox + kx];
                int t = ky * 3 + kx;
                #pragma unroll
                for (int j = 0; j < 4; j++)
                    acc[oy * 3 + ox][j] += v * wr[j][t];
              }
    }

    float s = 0.f, sq = 0.f;
    float* midb = g_mid + (long)(b * SS + hawa) * COUT * SS;
    #pragma unroll
    for (int oy = 0; oy < 3; oy++)
      #pragma unroll
      for (int ox = 0; ox < 3; ox++) {
        int hbwb = (py + oy) * S + (px + ox);
        #pragma unroll
        for (int j = 0; j < 4; j++) {
            float v = acc[oy * 3 + ox][j];
            s += v; sq += v * v;
            midb[(cg * 4 + j) * SS + hbwb] = v;
        }
      }
    atomicAdd(&s_red[(cg >> 1) * 2],     s);
    atomicAdd(&s_red[(cg >> 1) * 2 + 1], sq);
    __syncthreads();
    if (tid < 8) atomicAdd(&g_stats[b * 8 + tid], s_red[tid]);
}

// ---------------------------------------------------------------------------
__global__ void finalize_kernel(const float* __restrict__ gamma,
                                const float* __restrict__ beta) {
    int tid = threadIdx.x;
    if (tid >= BSZ * COUT) return;
    int b = tid >> 5, c = tid & 31, g = c >> 3;
    const float n = (float)(8 * SS * SS);
    float s  = g_stats[b * 8 + g * 2];
    float ss = g_stats[b * 8 + g * 2 + 1];
    float mean = s / n;
    float var  = ss / n - mean * mean;
    float sc = gamma[c] * rsqrtf(var + EPS);
    g_scale[tid] = sc;
    g_shift[tid] = beta[c] - mean * sc;
}

// ---------------------------------------------------------------------------
// conv1: 4x2 (ha,wa) tile x 32-lane chunk. 256 threads = 4 co-groups (8 co)
// x 8 positions (4x2, one each) x 8 lane-quads (float4). Per thread per ci:
// 27 LDS.128 feed 288 FFMAs (0.094 LDS/FMA). All strides power-of-2.
// Weights staged in 8-ci chunks. smem 107.8 KB -> 2 CTAs/SM (128-reg cap).
// Grid: BSZ * 72 tiles * 18 chunks (FIXED from R12's BSZ*144*18).
// ---------------------------------------------------------------------------
__global__ __launch_bounds__(256, 2)
void conv1_kernel(const float* __restrict__ w1, const float* __restrict__ b1,
                  float* __restrict__ out) {
    extern __shared__ float sm[];
    float* s_in = sm;                   // [24 coords][32 ci][32 lanes] = 24576
    float* s_w  = sm + 24576;           // [8 ci][9 tap][32 co] = 2304
    float* s_sc = sm + 24576 + 2304;    // 32
    float* s_sh = s_sc + 32;            // 32

    const int bid   = blockIdx.x;
    const int b     = bid / 1296;
    const int r     = bid - b * 1296;
    const int tile  = r / 18, chunk = r - (r / 18) * 18;
    const int ha0   = (tile / 12) * 4;      // 6 ha tiles of 4
    const int wa0   = (tile % 12) * 2;      // 12 wa tiles of 2
    const int lane0 = chunk * 32;
    const int tid   = threadIdx.x;

    if (tid < 32) {
        s_sc[tid] = g_scale[b * 32 + tid];
        s_sh[tid] = g_shift[b * 32 + tid];
    }
    __syncthreads();

    // stage inputs with GN + ReLU; zero-pad halo. 24 coords = 6 ha-rows x 4 wa-cols
    for (int idx = tid; idx < 24 * 32 * 32; idx += 256) {
        int lane  = idx & 31;
        int ci    = (idx >> 5) & 31;
        int coord = idx >> 10;
        int cy = ha0 - 1 + (coord >> 2);
        int cx = wa0 - 1 + (coord & 3);
        float v = 0.f;
        if ((unsigned)cy < S && (unsigned)cx < S) {
            float m = g_mid[((long)(b * SS + cy * S + cx) * COUT + ci) * SS + lane0 + lane];
            v = fmaxf(fmaf(m, s_sc[ci], s_sh[ci]), 0.f);
        }
        s_in[idx] = v;
    }

    const int cg  = tid >> 6;          // warp-uniform co-group (8 co)
    const int pos = (tid >> 3) & 7;    // 0..7 -> position in 4x2 tile
    const int lq  = tid & 7;           // 8 lane-quads x 4 lanes
    const int py  = pos >> 1;          // 0..3
    const int px  = pos & 1;           // 0..1
    const int l0  = lq * 4;
    const int co0 = cg * 8;

    float acc[8][4];
    #pragma unroll
    for (int j = 0; j < 8; j++) {
        float bb = __ldg(&b1[co0 + j]);
        acc[j][0] = bb; acc[j][1] = bb; acc[j][2] = bb; acc[j][3] = bb;
    }

    for (int c4 = 0; c4 < 4; c4++) {
        __syncthreads();   // s_in staged / prev s_w chunk consumed
        for (int i = tid; i < 8 * 9 * COUT; i += 256) {
            int ci = (i / 288) + c4 * 8; int t = (i >> 5) % 9; int co = i & 31;
            s_w[i] = w1[(co * COUT + ci) * 9 + t];
        }
        __syncthreads();

        for (int ci8 = 0; ci8 < 8; ci8++) {
            int ci = c4 * 8 + ci8;
            float4 in4[3][3];
            #pragma unroll
            for (int ky = 0; ky < 3; ky++)
                #pragma unroll
                for (int kx = 0; kx < 3; kx++) {
                    int coord = (py + ky) * 4 + px + kx;   // rows 0..5, cols 0..3
                    in4[ky][kx] = *(const float4*)&s_in[(coord << 10) + (ci << 5) + l0];
                }
            #pragma unroll
            for (int ky = 0; ky < 3; ky++)
              #pragma unroll
              for (int kx = 0; kx < 3; kx++) {
                int t = ky * 3 + kx;
                float4 wA = *(const float4*)&s_w[(ci8 << 8) + (ci8 << 5) + (t << 5) + co0];
                float4 wB = *(const float4*)&s_w[(ci8 << 8) + (ci8 << 5) + (t << 5) + co0 + 4];
                float4 v = in4[ky][kx];
                acc[0][0] += v.x * wA.x; acc[0][1] += v.y * wA.x; acc[0][2] += v.z * wA.x; acc[0][3] += v.w * wA.x;
                acc[1][0] += v.x * wA.y; acc[1][1] += v.y * wA.y; acc[1][2] += v.z * wA.y; acc[1][3] += v.w * wA.y;
                acc[2][0] += v.x * wA.z; acc[2][1] += v.y * wA.z; acc[2][2] += v.z * wA.z; acc[2][3] += v.w * wA.z;
                acc[3][0] += v.x * wA.w; acc[3][1] += v.y * wA.w; acc[3][2] += v.z * wA.w; acc[3][3] += v.w * wA.w;
                acc[4][0] += v.x * wB.x; acc[4][1] += v.y * wB.x; acc[4][2] += v.z * wB.x; acc[4][3] += v.w * wB.x;
                acc[5][0] += v.x * wB.y; acc[5][1] += v.y * wB.y; acc[5][2] += v.z * wB.y; acc[5][3] += v.w * wB.y;
                acc[6][0] += v.x * wB.z; acc[6][1] += v.y * wB.z; acc[6][2] += v.z * wB.z; acc[6][3] += v.w * wB.z;
                acc[7][0] += v.x * wB.w; acc[7][1] += v.y * wB.w; acc[7][2] += v.z * wB.w; acc[7][3] += v.w * wB.w;
              }
        }
    }

    const int hawa = (ha0 + py) * S + wa0 + px;
    #pragma unroll
    for (int j = 0; j < 8; j++) {
        float4 o = make_float4(acc[j][0], acc[j][1], acc[j][2], acc[j][3]);
        *(float4*)&out[((long)(b * COUT + co0 + j) * SS + hawa) * SS + lane0 + l0] = o;
    }
}

// ---------------------------------------------------------------------------
extern "C" void kernel_launch(void* const* d_in, const int* in_sizes, int n_in,
                              void* d_out, int out_size) {
    const float* x   = (const float*)d_in[0];
    const float* w1  = (const float*)d_in[1];
    const float* b1  = (const float*)d_in[2];
    const float* w2  = (const float*)d_in[3];
    const float* b2  = (const float*)d_in[4];
    const float* gam = (const float*)d_in[5];
    const float* bet = (const float*)d_in[6];
    float* out = (float*)d_out;

    const int smem2 = (10816 + 4608 + 8) * 4;            // 61,728 B
    const int smem1 = (24576 + 2304 + 64) * 4;           // 107,776 B
    cudaFuncSetAttribute(conv2_kernel, cudaFuncAttributeMaxDynamicSharedMemorySize, smem2);
    cudaFuncSetAttribute(conv1_kernel, cudaFuncAttributeMaxDynamicSharedMemorySize, smem1);

    zero_stats_kernel<<<1, 64>>>();
    conv2_kernel<<<BSZ * SS, 512, smem2>>>(x, w2, b2);
    finalize_kernel<<<1, 256>>>(gam, bet);
    conv1_kernel<<<BSZ * 72 * 18, 256, smem1>>>(w1, b1, out);   // 10368 blocks
}

// round 15
// speedup vs baseline: 1.4385x; 1.4209x over previous
#include <cuda_runtime.h>

#define CIN  16
#define COUT 32
#define BSZ  8
#define S    24
#define SS   576
#define EPS  1e-5f

__device__ float g_mid[BSZ * SS * COUT * SS];
__device__ float g_stats[BSZ * 4 * 2];
__device__ float g_scale[BSZ * COUT];
__device__ float g_shift[BSZ * COUT];

__global__ void zero_stats_kernel() {
    if (threadIdx.x < BSZ * 8) g_stats[threadIdx.x] = 0.f;
}

// ---------------------------------------------------------------------------
// conv2: identical to the passing R6/R9 version.
// ---------------------------------------------------------------------------
__global__ __launch_bounds__(512, 1)
void conv2_kernel(const float* __restrict__ x, const float* __restrict__ w2,
                  const float* __restrict__ b2) {
    extern __shared__ float sm[];
    float* s_img = sm;                  // [16][26][26] = 10816
    float* s_w   = sm + 10816;          // [ci][tap][co] = 4608
    float* s_red = sm + 10816 + 4608;   // 8

    const int bid  = blockIdx.x;
    const int b    = bid / SS;
    const int hawa = bid % SS;
    const int tid  = threadIdx.x;

    if (tid < 8) s_red[tid] = 0.f;
    for (int i = tid; i < CIN * 26 * 26; i += 512) s_img[i] = 0.f;
    for (int i = tid; i < CIN * 9 * COUT; i += 512) {
        int ci = i / 288; int tap = (i >> 5) % 9; int co = i & 31;
        s_w[i] = w2[(co * CIN + ci) * 9 + tap];
    }
    __syncthreads();
    for (int i = tid; i < CIN * SS; i += 512) {
        int ci = i / SS; int p = i - ci * SS;
        int hb = p / S, wb = p - hb * S;
        s_img[ci * 676 + (hb + 1) * 26 + (wb + 1)] =
            x[(((long)b * CIN + ci) * SS + hawa) * SS + p];
    }
    __syncthreads();

    const int cg = tid >> 6;
    const int pt = tid & 63;
    const int py = (pt >> 3) * 3;
    const int px = (pt & 7) * 3;

    float acc[9][4];
    #pragma unroll
    for (int j = 0; j < 4; j++) {
        float bb = __ldg(&b2[cg * 4 + j]);
        #pragma unroll
        for (int p = 0; p < 9; p++) acc[p][j] = bb;
    }

    for (int ci = 0; ci < CIN; ci++) {
        float wr[4][9];
        #pragma unroll
        for (int t = 0; t < 9; t++) {
            float4 wv = *(const float4*)&s_w[(ci * 9 + t) * 32 + cg * 4];
            wr[0][t] = wv.x; wr[1][t] = wv.y; wr[2][t] = wv.z; wr[3][t] = wv.w;
        }
        float in[5][5];
        #pragma unroll
        for (int dy = 0; dy < 5; dy++)
            #pragma unroll
            for (int dx = 0; dx < 5; dx++)
                in[dy][dx] = s_img[ci * 676 + (py + dy) * 26 + (px + dx)];
        #pragma unroll
        for (int oy = 0; oy < 3; oy++)
          #pragma unroll
          for (int ox = 0; ox < 3; ox++)
            #pragma unroll
            for (int ky = 0; ky < 3; ky++)
              #pragma unroll
              for (int kx = 0; kx < 3; kx++) {
                float v = in[oy + ky][ox + kx];
                int t = ky * 3 + kx;
                #pragma unroll
                for (int j = 0; j < 4; j++)
                    acc[oy * 3 + ox][j] += v * wr[j][t];
              }
    }

    float s = 0.f, sq = 0.f;
    float* midb = g_mid + (long)(b * SS + hawa) * COUT * SS;
    #pragma unroll
    for (int oy = 0; oy < 3; oy++)
      #pragma unroll
      for (int ox = 0; ox < 3; ox++) {
        int hbwb = (py + oy) * S + (px + ox);
        #pragma unroll
        for (int j = 0; j < 4; j++) {
            float v = acc[oy * 3 + ox][j];
            s += v; sq += v * v;
            midb[(cg * 4 + j) * SS + hbwb] = v;
        }
      }
    atomicAdd(&s_red[(cg >> 1) * 2],     s);
    atomicAdd(&s_red[(cg >> 1) * 2 + 1], sq);
    __syncthreads();
    if (tid < 8) atomicAdd(&g_stats[b * 8 + tid], s_red[tid]);
}

// ---------------------------------------------------------------------------
__global__ void finalize_kernel(const float* __restrict__ gamma,
                                const float* __restrict__ beta) {
    int tid = threadIdx.x;
    if (tid >= BSZ * COUT) return;
    int b = tid >> 5, c = tid & 31, g = c >> 3;
    const float n = (float)(8 * SS * SS);
    float s  = g_stats[b * 8 + g * 2];
    float ss = g_stats[b * 8 + g * 2 + 1];
    float mean = s / n;
    float var  = ss / n - mean * mean;
    float sc = gamma[c] * rsqrtf(var + EPS);
    g_scale[tid] = sc;
    g_shift[tid] = beta[c] - mean * sc;
}

// ---------------------------------------------------------------------------
// conv1: 2x2 (ha,wa) tile x 32-lane chunk. 256 threads = 8 co-groups (4 co)
// x 2 pcol x 16 lane-pairs; each thread owns 2 VERTICAL positions.
// Per thread per ci: 12 LDS.64 + 9 LDS.128 (60 reg-phases) feed 144 FFMAs
// -> FMA-bound. ~55 live regs -> clean banking. Full weights resident,
// no chunk syncs. smem 100.3 KB -> 2 CTAs/SM (16 warps).
// Grid: 8 b x 144 tiles x 18 chunks = 20736; b = bid/2592 <= 7. CHECKED.
// ---------------------------------------------------------------------------
__global__ __launch_bounds__(256, 2)
void conv1_kernel(const float* __restrict__ w1, const float* __restrict__ b1,
                  float* __restrict__ out) {
    extern __shared__ float sm[];
    float* s_in = sm;                   // [16 coords][32 ci][32 lanes] = 16384
    float* s_w  = sm + 16384;           // [32 ci][9 tap][32 co] = 9216
    float* s_sc = sm + 16384 + 9216;    // 32
    float* s_sh = s_sc + 32;            // 32

    const int bid   = blockIdx.x;
    const int b     = bid / 2592;                    // 2592 = 144*18
    const int r     = bid - b * 2592;
    const int tile  = r / 18, chunk = r - (r / 18) * 18;
    const int ha0   = (tile / 12) * 2, wa0 = (tile % 12) * 2;
    const int lane0 = chunk * 32;
    const int tid   = threadIdx.x;

    if (tid < 32) {
        s_sc[tid] = g_scale[b * 32 + tid];
        s_sh[tid] = g_shift[b * 32 + tid];
    }
    // weights: s_w[(ci*9+t)*32+co] = w1[(co*32+ci)*9+t]
    for (int i = tid; i < COUT * 9 * COUT; i += 256) {
        int ci = i / 288; int t = (i >> 5) % 9; int co = i & 31;
        s_w[i] = w1[(co * COUT + ci) * 9 + t];
    }
    __syncthreads();   // s_sc/s_sh ready before staging uses them

    // stage inputs with GN + ReLU via float4; zero-pad halo.
    // 16 coords = 4 halo-rows x 4 halo-cols. 4096 float4s / 256 thr.
    for (int idx4 = tid; idx4 < 16 * 32 * 8; idx4 += 256) {
        int l4    = idx4 & 7;            // float4 index within 32 lanes
        int ci    = (idx4 >> 3) & 31;
        int coord = idx4 >> 8;           // 0..15
        int cy = ha0 - 1 + (coord >> 2);
        int cx = wa0 - 1 + (coord & 3);
        float4 v = make_float4(0.f, 0.f, 0.f, 0.f);
        if ((unsigned)cy < S && (unsigned)cx < S) {
            float4 m = *(const float4*)&g_mid[
                ((long)(b * SS + cy * S + cx) * COUT + ci) * SS + lane0 + l4 * 4];
            float sc = s_sc[ci], sh = s_sh[ci];
            v.x = fmaxf(fmaf(m.x, sc, sh), 0.f);
            v.y = fmaxf(fmaf(m.y, sc, sh), 0.f);
            v.z = fmaxf(fmaf(m.z, sc, sh), 0.f);
            v.w = fmaxf(fmaf(m.w, sc, sh), 0.f);
        }
        *(float4*)&s_in[(coord << 10) + (ci << 5) + l4 * 4] = v;
    }
    __syncthreads();

    const int cg   = tid >> 5;         // 0..7, warp-uniform; co0 = cg*4
    const int pcol = (tid >> 4) & 1;   // output column within 2x2 tile
    const int lg   = tid & 15;         // 16 lane-pairs
    const int l0   = lg * 2;
    const int co0  = cg * 4;

    float acc[16];                     // [co j][pos pr][lane ln] = j*4+pr*2+ln
    #pragma unroll
    for (int j = 0; j < 4; j++) {
        float bb = __ldg(&b1[co0 + j]);
        acc[j * 4 + 0] = bb; acc[j * 4 + 1] = bb;
        acc[j * 4 + 2] = bb; acc[j * 4 + 3] = bb;
    }

    for (int ci = 0; ci < COUT; ci++) {
        // inputs: halo rows 0..3, cols pcol..pcol+2 (coord = ry*4 + pcol + kx)
        float2 in2[4][3];
        #pragma unroll
        for (int ry = 0; ry < 4; ry++)
            #pragma unroll
            for (int kx = 0; kx < 3; kx++) {
                int coord = ry * 4 + pcol + kx;
                in2[ry][kx] = *(const float2*)&s_in[(coord << 10) + (ci << 5) + l0];
            }
        #pragma unroll
        for (int ky = 0; ky < 3; ky++)
          #pragma unroll
          for (int kx = 0; kx < 3; kx++) {
            int t = ky * 3 + kx;
            float4 wv = *(const float4*)&s_w[(ci * 9 + t) * 32 + co0];
            float2 a = in2[ky][kx];        // pos 0 (row ky)
            float2 c = in2[ky + 1][kx];    // pos 1 (row ky+1)
            acc[0]  += a.x * wv.x; acc[1]  += a.y * wv.x;
            acc[2]  += c.x * wv.x; acc[3]  += c.y * wv.x;
            acc[4]  += a.x * wv.y; acc[5]  += a.y * wv.y;
            acc[6]  += c.x * wv.y; acc[7]  += c.y * wv.y;
            acc[8]  += a.x * wv.z; acc[9]  += a.y * wv.z;
            acc[10] += c.x * wv.z; acc[11] += c.y * wv.z;
            acc[12] += a.x * wv.w; acc[13] += a.y * wv.w;
            acc[14] += c.x * wv.w; acc[15] += c.y * wv.w;
          }
    }

    #pragma unroll
    for (int j = 0; j < 4; j++)
      #pragma unroll
      for (int pr = 0; pr < 2; pr++) {
        int hawa = (ha0 + pr) * S + wa0 + pcol;
        float2 o = make_float2(acc[j * 4 + pr * 2], acc[j * 4 + pr * 2 + 1]);
        *(float2*)&out[((long)(b * COUT + co0 + j) * SS + hawa) * SS + lane0 + l0] = o;
      }
}

// ---------------------------------------------------------------------------
extern "C" void kernel_launch(void* const* d_in, const int* in_sizes, int n_in,
                              void* d_out, int out_size) {
    const float* x   = (const float*)d_in[0];
    const float* w1  = (const float*)d_in[1];
    const float* b1  = (const float*)d_in[2];
    const float* w2  = (const float*)d_in[3];
    const float* b2  = (const float*)d_in[4];
    const float* gam = (const float*)d_in[5];
    const float* bet = (const float*)d_in[6];
    float* out = (float*)d_out;

    const int smem2 = (10816 + 4608 + 8) * 4;            // 61,728 B
    const int smem1 = (16384 + 9216 + 64) * 4;           // 102,656 B
    cudaFuncSetAttribute(conv2_kernel, cudaFuncAttributeMaxDynamicSharedMemorySize, smem2);
    cudaFuncSetAttribute(conv1_kernel, cudaFuncAttributeMaxDynamicSharedMemorySize, smem1);

    zero_stats_kernel<<<1, 64>>>();
    conv2_kernel<<<BSZ * SS, 512, smem2>>>(x, w2, b2);
    finalize_kernel<<<1, 256>>>(gam, bet);
    conv1_kernel<<<BSZ * 144 * 18, 256, smem1>>>(w1, b1, out);   // 8*2592 = 20736
}

// round 16
// speedup vs baseline: 1.6627x; 1.1559x over previous
#include <cuda_runtime.h>

#define CIN  16
#define COUT 32
#define BSZ  8
#define S    24
#define SS   576
#define EPS  1e-5f

__device__ float g_mid[BSZ * SS * COUT * SS];
__device__ float g_stats[BSZ * 4 * 2];
__device__ float g_scale[BSZ * COUT];
__device__ float g_shift[BSZ * COUT];

__global__ void zero_stats_kernel() {
    if (threadIdx.x < BSZ * 8) g_stats[threadIdx.x] = 0.f;
}

// ---------------------------------------------------------------------------
// conv2: identical to the passing R6/R9/R14 version.
// ---------------------------------------------------------------------------
__global__ __launch_bounds__(512, 1)
void conv2_kernel(const float* __restrict__ x, const float* __restrict__ w2,
                  const float* __restrict__ b2) {
    extern __shared__ float sm[];
    float* s_img = sm;                  // [16][26][26] = 10816
    float* s_w   = sm + 10816;          // [ci][tap][co] = 4608
    float* s_red = sm + 10816 + 4608;   // 8

    const int bid  = blockIdx.x;
    const int b    = bid / SS;
    const int hawa = bid % SS;
    const int tid  = threadIdx.x;

    if (tid < 8) s_red[tid] = 0.f;
    for (int i = tid; i < CIN * 26 * 26; i += 512) s_img[i] = 0.f;
    for (int i = tid; i < CIN * 9 * COUT; i += 512) {
        int ci = i / 288; int tap = (i >> 5) % 9; int co = i & 31;
        s_w[i] = w2[(co * CIN + ci) * 9 + tap];
    }
    __syncthreads();
    for (int i = tid; i < CIN * SS; i += 512) {
        int ci = i / SS; int p = i - ci * SS;
        int hb = p / S, wb = p - hb * S;
        s_img[ci * 676 + (hb + 1) * 26 + (wb + 1)] =
            x[(((long)b * CIN + ci) * SS + hawa) * SS + p];
    }
    __syncthreads();

    const int cg = tid >> 6;
    const int pt = tid & 63;
    const int py = (pt >> 3) * 3;
    const int px = (pt & 7) * 3;

    float acc[9][4];
    #pragma unroll
    for (int j = 0; j < 4; j++) {
        float bb = __ldg(&b2[cg * 4 + j]);
        #pragma unroll
        for (int p = 0; p < 9; p++) acc[p][j] = bb;
    }

    for (int ci = 0; ci < CIN; ci++) {
        float wr[4][9];
        #pragma unroll
        for (int t = 0; t < 9; t++) {
            float4 wv = *(const float4*)&s_w[(ci * 9 + t) * 32 + cg * 4];
            wr[0][t] = wv.x; wr[1][t] = wv.y; wr[2][t] = wv.z; wr[3][t] = wv.w;
        }
        float in[5][5];
        #pragma unroll
        for (int dy = 0; dy < 5; dy++)
            #pragma unroll
            for (int dx = 0; dx < 5; dx++)
                in[dy][dx] = s_img[ci * 676 + (py + dy) * 26 + (px + dx)];
        #pragma unroll
        for (int oy = 0; oy < 3; oy++)
          #pragma unroll
          for (int ox = 0; ox < 3; ox++)
            #pragma unroll
            for (int ky = 0; ky < 3; ky++)
              #pragma unroll
              for (int kx = 0; kx < 3; kx++) {
                float v = in[oy + ky][ox + kx];
                int t = ky * 3 + kx;
                #pragma unroll
                for (int j = 0; j < 4; j++)
                    acc[oy * 3 + ox][j] += v * wr[j][t];
              }
    }

    float s = 0.f, sq = 0.f;
    float* midb = g_mid + (long)(b * SS + hawa) * COUT * SS;
    #pragma unroll
    for (int oy = 0; oy < 3; oy++)
      #pragma unroll
      for (int ox = 0; ox < 3; ox++) {
        int hbwb = (py + oy) * S + (px + ox);
        #pragma unroll
        for (int j = 0; j < 4; j++) {
            float v = acc[oy * 3 + ox][j];
            s += v; sq += v * v;
            midb[(cg * 4 + j) * SS + hbwb] = v;
        }
      }
    atomicAdd(&s_red[(cg >> 1) * 2],     s);
    atomicAdd(&s_red[(cg >> 1) * 2 + 1], sq);
    __syncthreads();
    if (tid < 8) atomicAdd(&g_stats[b * 8 + tid], s_red[tid]);
}

// ---------------------------------------------------------------------------
__global__ void finalize_kernel(const float* __restrict__ gamma,
                                const float* __restrict__ beta) {
    int tid = threadIdx.x;
    if (tid >= BSZ * COUT) return;
    int b = tid >> 5, c = tid & 31, g = c >> 3;
    const float n = (float)(8 * SS * SS);
    float s  = g_stats[b * 8 + g * 2];
    float ss = g_stats[b * 8 + g * 2 + 1];
    float mean = s / n;
    float var  = ss / n - mean * mean;
    float sc = gamma[c] * rsqrtf(var + EPS);
    g_scale[tid] = sc;
    g_shift[tid] = beta[c] - mean * sc;
}

// ---------------------------------------------------------------------------
// conv1: 4x2 (ha,wa) tile x 32-lane chunk. 256 threads = 4 co-groups (8 co)
// x 2 row-pairs x 2 cols x 16 lane-pairs. Each thread: 8 co x 2 vert pos x
// 2 lanes = 32 outputs; per ci: 12 LDS.64 + 18 bcast LDS.128 feed 288 FMA.
// float2 inputs + flat acc keep ~85 regs (R13's banking failure avoided).
// Weights staged in 8-ci chunks; smem 107.8 KB -> 2 CTAs/SM.
// Grid: 8 b x 72 tiles x 18 chunks = 10368; b = bid/1296 <= 7. CHECKED.
// ---------------------------------------------------------------------------
__global__ __launch_bounds__(256, 2)
void conv1_kernel(const float* __restrict__ w1, const float* __restrict__ b1,
                  float* __restrict__ out) {
    extern __shared__ float sm[];
    float* s_in = sm;                   // [24 coords][32 ci][32 lanes] = 24576
    float* s_w  = sm + 24576;           // [8 ci][9 tap][32 co] = 2304
    float* s_sc = sm + 24576 + 2304;    // 32
    float* s_sh = s_sc + 32;            // 32

    const int bid   = blockIdx.x;
    const int b     = bid / 1296;                    // 1296 = 72*18
    const int r     = bid - b * 1296;
    const int tile  = r / 18, chunk = r - (r / 18) * 18;
    const int ha0   = (tile / 12) * 4;      // 6 ha tiles of 4 rows
    const int wa0   = (tile % 12) * 2;      // 12 wa tiles of 2 cols
    const int lane0 = chunk * 32;
    const int tid   = threadIdx.x;

    if (tid < 32) {
        s_sc[tid] = g_scale[b * 32 + tid];
        s_sh[tid] = g_shift[b * 32 + tid];
    }
    __syncthreads();   // s_sc/s_sh ready before staging

    // stage inputs with GN + ReLU via float4; zero-pad halo.
    // 24 coords = 6 halo-rows x 4 halo-cols; 6144 float4s / 256 thr.
    for (int idx4 = tid; idx4 < 24 * 32 * 8; idx4 += 256) {
        int l4    = idx4 & 7;
        int ci    = (idx4 >> 3) & 31;
        int coord = idx4 >> 8;           // 0..23
        int cy = ha0 - 1 + (coord >> 2);
        int cx = wa0 - 1 + (coord & 3);
        float4 v = make_float4(0.f, 0.f, 0.f, 0.f);
        if ((unsigned)cy < S && (unsigned)cx < S) {
            float4 m = *(const float4*)&g_mid[
                ((long)(b * SS + cy * S + cx) * COUT + ci) * SS + lane0 + l4 * 4];
            float sc = s_sc[ci], sh = s_sh[ci];
            v.x = fmaxf(fmaf(m.x, sc, sh), 0.f);
            v.y = fmaxf(fmaf(m.y, sc, sh), 0.f);
            v.z = fmaxf(fmaf(m.z, sc, sh), 0.f);
            v.w = fmaxf(fmaf(m.w, sc, sh), 0.f);
        }
        *(float4*)&s_in[(coord << 10) + (ci << 5) + l4 * 4] = v;
    }

    const int cg  = tid >> 6;          // 0..3 warp-uniform; co0 = cg*8
    const int rp2 = (tid >> 5) & 1;    // row-pair: output rows 2*rp2, 2*rp2+1
    const int pc  = (tid >> 4) & 1;    // output column
    const int lg  = tid & 15;          // 16 lane-pairs
    const int l0  = lg * 2;
    const int co0 = cg * 8;

    float acc[32];                     // [co j 0..7][pr 0..1][ln 0..1] -> j*4+pr*2+ln
    #pragma unroll
    for (int j = 0; j < 8; j++) {
        float bb = __ldg(&b1[co0 + j]);
        acc[j * 4 + 0] = bb; acc[j * 4 + 1] = bb;
        acc[j * 4 + 2] = bb; acc[j * 4 + 3] = bb;
    }

    for (int c4 = 0; c4 < 4; c4++) {
        __syncthreads();   // s_in staged (first iter) / prev s_w consumed
        for (int i = tid; i < 8 * 9 * COUT; i += 256) {
            int ci = (i / 288) + c4 * 8; int t = (i >> 5) % 9; int co = i & 31;
            s_w[i] = w1[(co * COUT + ci) * 9 + t];
        }
        __syncthreads();

        for (int ci8 = 0; ci8 < 8; ci8++) {
            int ci = c4 * 8 + ci8;
            // inputs: halo rows 2*rp2 .. 2*rp2+3 (local r=0..3), cols pc..pc+2
            float2 in2[4][3];
            #pragma unroll
            for (int rr = 0; rr < 4; rr++)
                #pragma unroll
                for (int kx = 0; kx < 3; kx++) {
                    int coord = (2 * rp2 + rr) * 4 + pc + kx;
                    in2[rr][kx] = *(const float2*)&s_in[(coord << 10) + (ci << 5) + l0];
                }
            #pragma unroll
            for (int ky = 0; ky < 3; ky++)
              #pragma unroll
              for (int kx = 0; kx < 3; kx++) {
                int t = ky * 3 + kx;
                float4 wA = *(const float4*)&s_w[(ci8 * 9 + t) * 32 + co0];
                float4 wB = *(const float4*)&s_w[(ci8 * 9 + t) * 32 + co0 + 4];
                float2 a = in2[ky][kx];        // output row pr=0
                float2 c = in2[ky + 1][kx];    // output row pr=1
                acc[0]  += a.x * wA.x; acc[1]  += a.y * wA.x;
                acc[2]  += c.x * wA.x; acc[3]  += c.y * wA.x;
                acc[4]  += a.x * wA.y; acc[5]  += a.y * wA.y;
                acc[6]  += c.x * wA.y; acc[7]  += c.y * wA.y;
                acc[8]  += a.x * wA.z; acc[9]  += a.y * wA.z;
                acc[10] += c.x * wA.z; acc[11] += c.y * wA.z;
                acc[12] += a.x * wA.w; acc[13] += a.y * wA.w;
                acc[14] += c.x * wA.w; acc[15] += c.y * wA.w;
                acc[16] += a.x * wB.x; acc[17] += a.y * wB.x;
                acc[18] += c.x * wB.x; acc[19] += c.y * wB.x;
                acc[20] += a.x * wB.y; acc[21] += a.y * wB.y;
                acc[22] += c.x * wB.y; acc[23] += c.y * wB.y;
                acc[24] += a.x * wB.z; acc[25] += a.y * wB.z;
                acc[26] += c.x * wB.z; acc[27] += c.y * wB.z;
                acc[28] += a.x * wB.w; acc[29] += a.y * wB.w;
                acc[30] += c.x * wB.w; acc[31] += c.y * wB.w;
              }
        }
    }

    #pragma unroll
    for (int j = 0; j < 8; j++)
      #pragma unroll
      for (int pr = 0; pr < 2; pr++) {
        int hawa = (ha0 + 2 * rp2 + pr) * S + wa0 + pc;
        float2 o = make_float2(acc[j * 4 + pr * 2], acc[j * 4 + pr * 2 + 1]);
        *(float2*)&out[((long)(b * COUT + co0 + j) * SS + hawa) * SS + lane0 + l0] = o;
      }
}

// ---------------------------------------------------------------------------
extern "C" void kernel_launch(void* const* d_in, const int* in_sizes, int n_in,
                              void* d_out, int out_size) {
    const float* x   = (const float*)d_in[0];
    const float* w1  = (const float*)d_in[1];
    const float* b1  = (const float*)d_in[2];
    const float* w2  = (const float*)d_in[3];
    const float* b2  = (const float*)d_in[4];
    const float* gam = (const float*)d_in[5];
    const float* bet = (const float*)d_in[6];
    float* out = (float*)d_out;

    const int smem2 = (10816 + 4608 + 8) * 4;            // 61,728 B
    const int smem1 = (24576 + 2304 + 64) * 4;           // 107,776 B
    cudaFuncSetAttribute(conv2_kernel, cudaFuncAttributeMaxDynamicSharedMemorySize, smem2);
    cudaFuncSetAttribute(conv1_kernel, cudaFuncAttributeMaxDynamicSharedMemorySize, smem1);

    zero_stats_kernel<<<1, 64>>>();
    conv2_kernel<<<BSZ * SS, 512, smem2>>>(x, w2, b2);
    finalize_kernel<<<1, 256>>>(gam, bet);
    conv1_kernel<<<BSZ * 72 * 18, 256, smem1>>>(w1, b1, out);   // 10368 blocks
}

// round 17
// speedup vs baseline: 1.7158x; 1.0319x over previous
#include <cuda_runtime.h>

#define CIN  16
#define COUT 32
#define BSZ  8
#define S    24
#define SS   576
#define EPS  1e-5f

typedef unsigned long long u64;

__device__ float g_mid[BSZ * SS * COUT * SS];
__device__ float g_stats[BSZ * 4 * 2];
__device__ float g_scale[BSZ * COUT];
__device__ float g_shift[BSZ * COUT];

__device__ __forceinline__ u64 fma2(u64 a, u64 b, u64 c) {
    u64 d;
    asm("fma.rn.f32x2 %0, %1, %2, %3;" : "=l"(d) : "l"(a), "l"(b), "l"(c));
    return d;
}
__device__ __forceinline__ u64 pack2(float lo, float hi) {
    u64 r;
    asm("mov.b64 %0, {%1, %2};" : "=l"(r) : "f"(lo), "f"(hi));
    return r;
}
__device__ __forceinline__ void unpack2(u64 v, float& lo, float& hi) {
    asm("mov.b64 {%0, %1}, %2;" : "=f"(lo), "=f"(hi) : "l"(v));
}

__global__ void zero_stats_kernel() {
    if (threadIdx.x < BSZ * 8) g_stats[threadIdx.x] = 0.f;
}

// ---------------------------------------------------------------------------
// conv2: identical to the passing R6/R9/R15 version.
// ---------------------------------------------------------------------------
__global__ __launch_bounds__(512, 1)
void conv2_kernel(const float* __restrict__ x, const float* __restrict__ w2,
                  const float* __restrict__ b2) {
    extern __shared__ float sm[];
    float* s_img = sm;                  // [16][26][26] = 10816
    float* s_w   = sm + 10816;          // [ci][tap][co] = 4608
    float* s_red = sm + 10816 + 4608;   // 8

    const int bid  = blockIdx.x;
    const int b    = bid / SS;
    const int hawa = bid % SS;
    const int tid  = threadIdx.x;

    if (tid < 8) s_red[tid] = 0.f;
    for (int i = tid; i < CIN * 26 * 26; i += 512) s_img[i] = 0.f;
    for (int i = tid; i < CIN * 9 * COUT; i += 512) {
        int ci = i / 288; int tap = (i >> 5) % 9; int co = i & 31;
        s_w[i] = w2[(co * CIN + ci) * 9 + tap];
    }
    __syncthreads();
    for (int i = tid; i < CIN * SS; i += 512) {
        int ci = i / SS; int p = i - ci * SS;
        int hb = p / S, wb = p - hb * S;
        s_img[ci * 676 + (hb + 1) * 26 + (wb + 1)] =
            x[(((long)b * CIN + ci) * SS + hawa) * SS + p];
    }
    __syncthreads();

    const int cg = tid >> 6;
    const int pt = tid & 63;
    const int py = (pt >> 3) * 3;
    const int px = (pt & 7) * 3;

    float acc[9][4];
    #pragma unroll
    for (int j = 0; j < 4; j++) {
        float bb = __ldg(&b2[cg * 4 + j]);
        #pragma unroll
        for (int p = 0; p < 9; p++) acc[p][j] = bb;
    }

    for (int ci = 0; ci < CIN; ci++) {
        float wr[4][9];
        #pragma unroll
        for (int t = 0; t < 9; t++) {
            float4 wv = *(const float4*)&s_w[(ci * 9 + t) * 32 + cg * 4];
            wr[0][t] = wv.x; wr[1][t] = wv.y; wr[2][t] = wv.z; wr[3][t] = wv.w;
        }
        float in[5][5];
        #pragma unroll
        for (int dy = 0; dy < 5; dy++)
            #pragma unroll
            for (int dx = 0; dx < 5; dx++)
                in[dy][dx] = s_img[ci * 676 + (py + dy) * 26 + (px + dx)];
        #pragma unroll
        for (int oy = 0; oy < 3; oy++)
          #pragma unroll
          for (int ox = 0; ox < 3; ox++)
            #pragma unroll
            for (int ky = 0; ky < 3; ky++)
              #pragma unroll
              for (int kx = 0; kx < 3; kx++) {
                float v = in[oy + ky][ox + kx];
                int t = ky * 3 + kx;
                #pragma unroll
                for (int j = 0; j < 4; j++)
                    acc[oy * 3 + ox][j] += v * wr[j][t];
              }
    }

    float s = 0.f, sq = 0.f;
    float* midb = g_mid + (long)(b * SS + hawa) * COUT * SS;
    #pragma unroll
    for (int oy = 0; oy < 3; oy++)
      #pragma unroll
      for (int ox = 0; ox < 3; ox++) {
        int hbwb = (py + oy) * S + (px + ox);
        #pragma unroll
        for (int j = 0; j < 4; j++) {
            float v = acc[oy * 3 + ox][j];
            s += v; sq += v * v;
            midb[(cg * 4 + j) * SS + hbwb] = v;
        }
      }
    atomicAdd(&s_red[(cg >> 1) * 2],     s);
    atomicAdd(&s_red[(cg >> 1) * 2 + 1], sq);
    __syncthreads();
    if (tid < 8) atomicAdd(&g_stats[b * 8 + tid], s_red[tid]);
}

// ---------------------------------------------------------------------------
__global__ void finalize_kernel(const float* __restrict__ gamma,
                                const float* __restrict__ beta) {
    int tid = threadIdx.x;
    if (tid >= BSZ * COUT) return;
    int b = tid >> 5, c = tid & 31, g = c >> 3;
    const float n = (float)(8 * SS * SS);
    float s  = g_stats[b * 8 + g * 2];
    float ss = g_stats[b * 8 + g * 2 + 1];
    float mean = s / n;
    float var  = ss / n - mean * mean;
    float sc = gamma[c] * rsqrtf(var + EPS);
    g_scale[tid] = sc;
    g_shift[tid] = beta[c] - mean * sc;
}

// ---------------------------------------------------------------------------
// conv1: R15 skeleton (4x2 tile, 32-lane chunk, 8-ci weight chunks, grid
// 8*72*18) with the inner loop converted to f32x2 FFMA2 packed over CO
// PAIRS: weights (co,co+1) read as native u64 from scalar s_w (no extra
// crossbar bytes); inputs duplicated (v,v) via register pack2 on ALU pipe.
// Per ci: 144 FFMA2 + 24 pack + 12 LDS.64 + 18 bcast LDS.128.
// ---------------------------------------------------------------------------
__global__ __launch_bounds__(256, 2)
void conv1_kernel(const float* __restrict__ w1, const float* __restrict__ b1,
                  float* __restrict__ out) {
    extern __shared__ float sm[];
    float* s_in = sm;                   // [24 coords][32 ci][32 lanes] = 24576
    float* s_w  = sm + 24576;           // [8 ci][9 tap][32 co] = 2304
    float* s_sc = sm + 24576 + 2304;    // 32
    float* s_sh = s_sc + 32;            // 32

    const int bid   = blockIdx.x;
    const int b     = bid / 1296;                    // 1296 = 72*18, b <= 7
    const int r     = bid - b * 1296;
    const int tile  = r / 18, chunk = r - (r / 18) * 18;
    const int ha0   = (tile / 12) * 4;      // 6 ha tiles of 4 rows
    const int wa0   = (tile % 12) * 2;      // 12 wa tiles of 2 cols
    const int lane0 = chunk * 32;
    const int tid   = threadIdx.x;

    if (tid < 32) {
        s_sc[tid] = g_scale[b * 32 + tid];
        s_sh[tid] = g_shift[b * 32 + tid];
    }
    __syncthreads();

    // stage inputs with GN + ReLU via float4; zero-pad halo.
    for (int idx4 = tid; idx4 < 24 * 32 * 8; idx4 += 256) {
        int l4    = idx4 & 7;
        int ci    = (idx4 >> 3) & 31;
        int coord = idx4 >> 8;           // 0..23
        int cy = ha0 - 1 + (coord >> 2);
        int cx = wa0 - 1 + (coord & 3);
        float4 v = make_float4(0.f, 0.f, 0.f, 0.f);
        if ((unsigned)cy < S && (unsigned)cx < S) {
            float4 m = *(const float4*)&g_mid[
                ((long)(b * SS + cy * S + cx) * COUT + ci) * SS + lane0 + l4 * 4];
            float sc = s_sc[ci], sh = s_sh[ci];
            v.x = fmaxf(fmaf(m.x, sc, sh), 0.f);
            v.y = fmaxf(fmaf(m.y, sc, sh), 0.f);
            v.z = fmaxf(fmaf(m.z, sc, sh), 0.f);
            v.w = fmaxf(fmaf(m.w, sc, sh), 0.f);
        }
        *(float4*)&s_in[(coord << 10) + (ci << 5) + l4 * 4] = v;
    }

    const int cg  = tid >> 6;          // 0..3 warp-uniform; co0 = cg*8
    const int rp2 = (tid >> 5) & 1;    // row-pair: output rows 2*rp2, 2*rp2+1
    const int pc  = (tid >> 4) & 1;    // output column
    const int lg  = tid & 15;          // 16 lane-pairs
    const int l0  = lg * 2;
    const int co0 = cg * 8;

    // acc2[cp*4 + pos*2 + lane] = u64 packing (co=co0+2cp, co0+2cp+1)
    u64 acc2[16];
    #pragma unroll
    for (int cp = 0; cp < 4; cp++) {
        u64 bb = pack2(__ldg(&b1[co0 + 2 * cp]), __ldg(&b1[co0 + 2 * cp + 1]));
        acc2[cp * 4 + 0] = bb; acc2[cp * 4 + 1] = bb;
        acc2[cp * 4 + 2] = bb; acc2[cp * 4 + 3] = bb;
    }

    for (int c4 = 0; c4 < 4; c4++) {
        __syncthreads();   // s_in staged (first iter) / prev s_w consumed
        for (int i = tid; i < 8 * 9 * COUT; i += 256) {
            int ci = (i / 288) + c4 * 8; int t = (i >> 5) % 9; int co = i & 31;
            s_w[i] = w1[(co * COUT + ci) * 9 + t];
        }
        __syncthreads();

        for (int ci8 = 0; ci8 < 8; ci8++) {
            int ci = c4 * 8 + ci8;
            // inputs: halo rows 2*rp2 .. 2*rp2+3, cols pc..pc+2; duplicate to u64
            u64 dup[4][3][2];
            #pragma unroll
            for (int rr = 0; rr < 4; rr++)
                #pragma unroll
                for (int kx = 0; kx < 3; kx++) {
                    int coord = (2 * rp2 + rr) * 4 + pc + kx;
                    float2 v = *(const float2*)&s_in[(coord << 10) + (ci << 5) + l0];
                    dup[rr][kx][0] = pack2(v.x, v.x);
                    dup[rr][kx][1] = pack2(v.y, v.y);
                }
            #pragma unroll
            for (int ky = 0; ky < 3; ky++)
              #pragma unroll
              for (int kx = 0; kx < 3; kx++) {
                int t = ky * 3 + kx;
                // co-pairs: (co0,co0+1),(co0+2,co0+3) then (+4..+7)
                ulonglong2 wA = *(const ulonglong2*)&s_w[(ci8 * 9 + t) * 32 + co0];
                ulonglong2 wB = *(const ulonglong2*)&s_w[(ci8 * 9 + t) * 32 + co0 + 4];
                u64 a0 = dup[ky][kx][0],     a1 = dup[ky][kx][1];      // pos 0
                u64 c0 = dup[ky + 1][kx][0], c1 = dup[ky + 1][kx][1];  // pos 1
                acc2[0]  = fma2(a0, wA.x, acc2[0]);
                acc2[1]  = fma2(a1, wA.x, acc2[1]);
                acc2[2]  = fma2(c0, wA.x, acc2[2]);
                acc2[3]  = fma2(c1, wA.x, acc2[3]);
                acc2[4]  = fma2(a0, wA.y, acc2[4]);
                acc2[5]  = fma2(a1, wA.y, acc2[5]);
                acc2[6]  = fma2(c0, wA.y, acc2[6]);
                acc2[7]  = fma2(c1, wA.y, acc2[7]);
                acc2[8]  = fma2(a0, wB.x, acc2[8]);
                acc2[9]  = fma2(a1, wB.x, acc2[9]);
                acc2[10] = fma2(c0, wB.x, acc2[10]);
                acc2[11] = fma2(c1, wB.x, acc2[11]);
                acc2[12] = fma2(a0, wB.y, acc2[12]);
                acc2[13] = fma2(a1, wB.y, acc2[13]);
                acc2[14] = fma2(c0, wB.y, acc2[14]);
                acc2[15] = fma2(c1, wB.y, acc2[15]);
              }
        }
    }

    // writeout: unpack co-pairs, store float2 (lane0, lane1) per co
    #pragma unroll
    for (int cp = 0; cp < 4; cp++)
      #pragma unroll
      for (int pr = 0; pr < 2; pr++) {
        float e0lo, e0hi, e1lo, e1hi;
        unpack2(acc2[cp * 4 + pr * 2 + 0], e0lo, e0hi);   // lane0: (co, co+1)
        unpack2(acc2[cp * 4 + pr * 2 + 1], e1lo, e1hi);   // lane1: (co, co+1)
        int hawa = (ha0 + 2 * rp2 + pr) * S + wa0 + pc;
        int coA = co0 + 2 * cp, coB = coA + 1;
        *(float2*)&out[((long)(b * COUT + coA) * SS + hawa) * SS + lane0 + l0] =
            make_float2(e0lo, e1lo);
        *(float2*)&out[((long)(b * COUT + coB) * SS + hawa) * SS + lane0 + l0] =
            make_float2(e0hi, e1hi);
      }
}

// ---------------------------------------------------------------------------
extern "C" void kernel_launch(void* const* d_in, const int* in_sizes, int n_in,
                              void* d_out, int out_size) {
    const float* x   = (const float*)d_in[0];
    const float* w1  = (const float*)d_in[1];
    const float* b1  = (const float*)d_in[2];
    const float* w2  = (const float*)d_in[3];
    const float* b2  = (const float*)d_in[4];
    const float* gam = (const float*)d_in[5];
    const float* bet = (const float*)d_in[6];
    float* out = (float*)d_out;

    const int smem2 = (10816 + 4608 + 8) * 4;            // 61,728 B
    const int smem1 = (24576 + 2304 + 64) * 4;           // 107,776 B
    cudaFuncSetAttribute(conv2_kernel, cudaFuncAttributeMaxDynamicSharedMemorySize, smem2);
    cudaFuncSetAttribute(conv1_kernel, cudaFuncAttributeMaxDynamicSharedMemorySize, smem1);

    zero_stats_kernel<<<1, 64>>>();
    conv2_kernel<<<BSZ * SS, 512, smem2>>>(x, w2, b2);
    finalize_kernel<<<1, 256>>>(gam, bet);
    conv1_kernel<<<BSZ * 72 * 18, 256, smem1>>>(w1, b1, out);   // 10368 blocks
}